// round 1
// baseline (speedup 1.0000x reference)
#include <cuda_runtime.h>
#include <math.h>

#define NN   10000
#define EE   320000
#define DIM  176
#define ATT  16
#define SHH  16
#define THH  4
#define NHH  20
#define VD   11
#define NSPH 16
#define RDIMC 16

typedef unsigned long long u64;

// ---------------- scratch (static device allocations) ----------------
__device__ float g_xi[NN * DIM];
__device__ float g_q [NN * NHH * ATT];
__device__ float g_k [NN * NHH * ATT];
__device__ float g_v [NN * DIM];
__device__ float g_mi[NN * DIM];
__device__ float g_Vi[NN * THH * NSPH];
__device__ float g_Y [EE * NSPH];
__device__ float g_rad[EE * RDIMC];
__device__ float g_G [NN * DIM];

// ---------------- helpers ----------------
__device__ __forceinline__ u64 pack2(float x, float y) {
    u64 r; asm("mov.b64 %0,{%1,%2};" : "=l"(r) : "f"(x), "f"(y)); return r;
}
__device__ __forceinline__ void fma2(u64& d, u64 a, u64 b) {
    asm("fma.rn.f32x2 %0, %1, %2, %3;" : "=l"(d) : "l"(a), "l"(b), "l"(d));
}
__device__ __forceinline__ float2 unpack2(u64 v) {
    float2 f; asm("mov.b64 {%0,%1},%2;" : "=f"(f.x), "=f"(f.y) : "l"(v)); return f;
}

// block reduction for blockDim=192 (6 warps)
__device__ __forceinline__ float block_sum_192(float v, float* red) {
    #pragma unroll
    for (int o = 16; o; o >>= 1) v += __shfl_xor_sync(0xffffffffu, v, o);
    if ((threadIdx.x & 31) == 0) red[threadIdx.x >> 5] = v;
    __syncthreads();
    float s = 0.f;
    if (threadIdx.x < 6) s = red[threadIdx.x];
    if (threadIdx.x < 32) {
        s += __shfl_xor_sync(0xffffffffu, s, 4);
        s += __shfl_xor_sync(0xffffffffu, s, 2);
        s += __shfl_xor_sync(0xffffffffu, s, 1);
        if (threadIdx.x == 0) red[0] = s;
    }
    __syncthreads();
    float r = red[0];
    __syncthreads();
    return r;
}

// ---------------- node embedding: xi = LN(z_table[species] @ w_species) ----------------
__global__ void node_embed_kernel(const int* __restrict__ species,
                                  const float* __restrict__ zt,
                                  const float* __restrict__ wsp) {
    __shared__ float sZ[16];
    __shared__ float red[8];
    int n = blockIdx.x;
    int t = threadIdx.x;
    if (t < 16) sZ[t] = zt[species[n] * 16 + t];
    __syncthreads();
    float val = 0.f;
    if (t < DIM) {
        #pragma unroll
        for (int z = 0; z < 16; z++) val += sZ[z] * wsp[z * DIM + t];
    }
    float mu = block_sum_192(val, red) * (1.f / DIM);
    float dx = (t < DIM) ? (val - mu) : 0.f;
    float var = block_sum_192(dx * dx, red) * (1.f / DIM);
    if (t < DIM) g_xi[n * DIM + t] = dx * rsqrtf(var + 1e-6f);
}

// ---------------- edge geometry: spherical harmonics + radial basis ----------------
__global__ void edge_geom_kernel(const float* __restrict__ dist,
                                 const float* __restrict__ vec) {
    int e = blockIdx.x * blockDim.x + threadIdx.x;
    if (e >= EE) return;
    float d = dist[e];
    float inv = 1.f / d;
    float x = vec[e * 3 + 0] * inv;
    float y = vec[e * 3 + 1] * inv;
    float z = vec[e * 3 + 2] * inv;
    const float s3  = 1.7320508075688772f;
    const float s15 = 3.872983346207417f;
    const float c1  = 0.7905694150420949f;  // sqrt(5/8)
    const float c2  = 0.6123724356957945f;  // sqrt(3/8)
    float x2 = x * x, y2 = y * y, z2 = z * z;
    float Y[16];
    Y[0]  = 1.f;
    Y[1]  = x; Y[2] = y; Y[3] = z;
    Y[4]  = s3 * x * y;
    Y[5]  = s3 * y * z;
    Y[6]  = 0.5f * (3.f * z2 - 1.f);
    Y[7]  = s3 * x * z;
    Y[8]  = 0.5f * s3 * (x2 - y2);
    Y[9]  = c1 * y * (3.f * x2 - y2);
    Y[10] = s15 * x * y * z;
    Y[11] = c2 * y * (5.f * z2 - 1.f);
    Y[12] = 0.5f * z * (5.f * z2 - 3.f);
    Y[13] = c2 * x * (5.f * z2 - 1.f);
    Y[14] = 0.5f * s15 * z * (x2 - y2);
    Y[15] = c1 * x * (x2 - 3.f * y2);
    float R[16];
    const float sigma = 0.28f;
    const float invs = 1.f / 0.28f;
    #pragma unroll
    for (int r = 0; r < 16; r++) {
        float c = 0.8f + sigma * (float)r;
        float tt = (d - c) * invs;
        R[r] = expf(-tt * tt);
    }
    float4* yo = reinterpret_cast<float4*>(g_Y + e * 16);
    float4* ro = reinterpret_cast<float4*>(g_rad + e * 16);
    #pragma unroll
    for (int i = 0; i < 4; i++) {
        yo[i] = make_float4(Y[4*i], Y[4*i+1], Y[4*i+2], Y[4*i+3]);
        ro[i] = make_float4(R[4*i], R[4*i+1], R[4*i+2], R[4*i+3]);
    }
}

// ---------------- zero scratch ----------------
__global__ void zero_kernel(int doVi) {
    int i = blockIdx.x * blockDim.x + threadIdx.x;
    if (i < NN * DIM) g_mi[i] = 0.f;
    if (doVi && i < NN * THH * NSPH) g_Vi[i] = 0.f;
}

// ---------------- SGEMM with packed f32x2 FMA ----------------
// C[M,Ncols] = concat(A[M,K1], A2[M,Ktot-K1]) @ B[Ktot,Ncols]
// BM=BN=128, BK=16, 256 threads, 8x8 per thread
__global__ __launch_bounds__(256) void sgemm_kernel(
    const float* __restrict__ A, const float* __restrict__ A2,
    int K1, int Ktot,
    const float* __restrict__ B, float* __restrict__ C,
    int M, int Ncols)
{
    __shared__ u64   As2[16][128];   // duplicated-pair A values
    __shared__ float Bs [16][128];
    int tid = threadIdx.x;
    int tx = tid & 15, ty = tid >> 4;
    int row0 = blockIdx.y * 128;
    int col0 = blockIdx.x * 128;
    u64 acc[8][4];
    #pragma unroll
    for (int i = 0; i < 8; i++)
        #pragma unroll
        for (int j = 0; j < 4; j++) acc[i][j] = 0ull;

    int nk = Ktot / 16;
    for (int kt = 0; kt < nk; ++kt) {
        int gkbase = kt * 16;
        // --- load A tile (128 rows x 16 k), 8 floats per thread ---
        {
            int r  = tid >> 1;
            int c0 = (tid & 1) * 8;
            int grow = row0 + r;
            const float* Ap; int stride; int koff;
            if (gkbase < K1) { Ap = A;  stride = K1;        koff = gkbase; }
            else             { Ap = A2; stride = Ktot - K1; koff = gkbase - K1; }
            float4 v0 = make_float4(0,0,0,0), v1 = make_float4(0,0,0,0);
            if (grow < M) {
                const float* src = Ap + (long long)grow * stride + koff + c0;
                v0 = *reinterpret_cast<const float4*>(src);
                v1 = *reinterpret_cast<const float4*>(src + 4);
            }
            As2[c0+0][r] = pack2(v0.x, v0.x);
            As2[c0+1][r] = pack2(v0.y, v0.y);
            As2[c0+2][r] = pack2(v0.z, v0.z);
            As2[c0+3][r] = pack2(v0.w, v0.w);
            As2[c0+4][r] = pack2(v1.x, v1.x);
            As2[c0+5][r] = pack2(v1.y, v1.y);
            As2[c0+6][r] = pack2(v1.z, v1.z);
            As2[c0+7][r] = pack2(v1.w, v1.w);
        }
        // --- load B tile (16 k x 128 cols), 8 floats per thread ---
        {
            int br = tid >> 4;
            int bc = (tid & 15) * 8;
            int gk = gkbase + br;
            int gcol = col0 + bc;
            float4 v0 = make_float4(0,0,0,0), v1 = make_float4(0,0,0,0);
            if (gcol < Ncols) {
                const float* src = B + (long long)gk * Ncols + gcol;
                v0 = *reinterpret_cast<const float4*>(src);
                v1 = *reinterpret_cast<const float4*>(src + 4);
            }
            *reinterpret_cast<float4*>(&Bs[br][bc])     = v0;
            *reinterpret_cast<float4*>(&Bs[br][bc + 4]) = v1;
        }
        __syncthreads();
        #pragma unroll
        for (int k = 0; k < 16; ++k) {
            u64 a[8];
            {
                const ulonglong2* p = reinterpret_cast<const ulonglong2*>(&As2[k][ty * 8]);
                ulonglong2 q0 = p[0], q1 = p[1], q2 = p[2], q3 = p[3];
                a[0]=q0.x; a[1]=q0.y; a[2]=q1.x; a[3]=q1.y;
                a[4]=q2.x; a[5]=q2.y; a[6]=q3.x; a[7]=q3.y;
            }
            u64 b[4];
            {
                const ulonglong2* p = reinterpret_cast<const ulonglong2*>(&Bs[k][tx * 8]);
                ulonglong2 w0 = p[0], w1 = p[1];
                b[0]=w0.x; b[1]=w0.y; b[2]=w1.x; b[3]=w1.y;
            }
            #pragma unroll
            for (int i = 0; i < 8; i++)
                #pragma unroll
                for (int j = 0; j < 4; j++)
                    fma2(acc[i][j], a[i], b[j]);
        }
        __syncthreads();
    }
    #pragma unroll
    for (int i = 0; i < 8; i++) {
        int gr = row0 + ty * 8 + i;
        if (gr >= M) continue;
        #pragma unroll
        for (int j = 0; j < 4; j++) {
            int gc = col0 + tx * 8 + j * 2;
            if (gc < Ncols) {
                float2 f = unpack2(acc[i][j]);
                *reinterpret_cast<float2*>(&C[(long long)gr * Ncols + gc]) = f;
            }
        }
    }
}

// ---------------- edge attention + scatter (warp per edge) ----------------
template<int LAYER>
__global__ void edge_attn_kernel(
    const int* __restrict__ src, const int* __restrict__ dst,
    const float* __restrict__ swtch,
    const float* __restrict__ pw1, const float* __restrict__ pb1,
    const float* __restrict__ pw2, const float* __restrict__ pb2)
{
    constexpr int UR = (LAYER == 0) ? 16 : 32;
    __shared__ float s_pw1[UR * 32];
    __shared__ float s_pw2[32 * 16];
    __shared__ float s_b1[32];
    __shared__ float s_b2[16];
    __shared__ float s_ur[8][32];
    __shared__ float s_Y[8][16];
    __shared__ float s_a[8][20];

    int tid = threadIdx.x;
    for (int i = tid; i < UR * 32; i += 256) s_pw1[i] = pw1[i];
    for (int i = tid; i < 512;     i += 256) s_pw2[i] = pw2[i];
    if (tid < 32) s_b1[tid] = pb1[tid];
    if (tid < 16) s_b2[tid] = pb2[tid];
    __syncthreads();

    int wid = tid >> 5, lane = tid & 31;
    for (int e = blockIdx.x * 8 + wid; e < EE; e += gridDim.x * 8) {
        int is = src[e], id = dst[e];
        if (lane < 16) {
            s_ur[wid][lane] = g_rad[e * 16 + lane];
            s_Y [wid][lane] = g_Y  [e * 16 + lane];
        }
        __syncwarp();
        if (LAYER == 1) {
            if (lane < 4) {
                const float* Vd = &g_Vi[id * 64 + lane * 16];
                const float* Vs = &g_Vi[is * 64 + lane * 16];
                float u0 = (Vd[0] + Vs[0]) * s_Y[wid][0];
                float u1 = 0.f, u2 = 0.f, u3 = 0.f;
                #pragma unroll
                for (int m = 1; m < 4; m++)  u1 += (Vd[m] - Vs[m]) * s_Y[wid][m];
                #pragma unroll
                for (int m = 4; m < 9; m++)  u2 += (Vd[m] + Vs[m]) * s_Y[wid][m];
                #pragma unroll
                for (int m = 9; m < 16; m++) u3 += (Vd[m] - Vs[m]) * s_Y[wid][m];
                s_ur[wid][16 + lane] = u0;
                s_ur[wid][20 + lane] = u1;
                s_ur[wid][24 + lane] = u2;
                s_ur[wid][28 + lane] = u3;
            }
            __syncwarp();
        }
        // MLP hidden (32 units, one per lane)
        float h = s_b1[lane];
        #pragma unroll
        for (int r = 0; r < UR; r++) h += s_ur[wid][r] * s_pw1[r * 32 + lane];
        h = h / (1.f + expf(-h));   // swish
        // w[d], every lane holds w[lane&15]
        int dl = lane & 15;
        float wv = s_b2[dl];
        #pragma unroll
        for (int j = 0; j < 32; j++)
            wv += __shfl_sync(0xffffffffu, h, j) * s_pw2[j * 16 + dl];
        // attention logits, 2 heads per pass (half-warp each)
        float sws = swtch[e] * 0.25f;
        const float* qr = &g_q[id * 320];
        const float* kr = &g_k[is * 320];
        int hh = lane >> 4;
        #pragma unroll
        for (int p = 0; p < 10; p++) {
            int hd = (p * 2 + hh) * 16 + dl;
            float pr = qr[hd] * kr[hd] * wv;
            pr += __shfl_xor_sync(0xffffffffu, pr, 1, 16);
            pr += __shfl_xor_sync(0xffffffffu, pr, 2, 16);
            pr += __shfl_xor_sync(0xffffffffu, pr, 4, 16);
            pr += __shfl_xor_sync(0xffffffffu, pr, 8, 16);
            if (dl == 0) s_a[wid][p * 2 + hh] = pr * sws;
        }
        __syncwarp();
        // scatter mi += a_s[h] * v[src]
        const float* vr = &g_v[is * 176];
        float* mr = &g_mi[(long long)id * 176];
        for (int t = lane; t < 176; t += 32) {
            int hidx = t / 11;
            atomicAdd(&mr[t], s_a[wid][hidx] * vr[t]);
        }
        // scatter Vi += a_t[t] * Y   (layer 0 only; Vi_old == 0)
        if (LAYER == 0) {
            for (int t2 = lane; t2 < 64; t2 += 32) {
                atomicAdd(&g_Vi[(long long)id * 64 + t2],
                          s_a[wid][16 + (t2 >> 4)] * s_Y[wid][t2 & 15]);
            }
        }
        __syncwarp();
    }
}

// ---------------- residual + LayerNorm ----------------
__global__ void resln_kernel(const float* __restrict__ ub, float* __restrict__ out, int toXi) {
    __shared__ float red[8];
    int n = blockIdx.x, t = threadIdx.x;
    float val = 0.f;
    if (t < DIM) val = g_xi[n * DIM + t] + g_G[n * DIM + t] + ub[t];
    float mu = block_sum_192(val, red) * (1.f / DIM);
    float dx = (t < DIM) ? (val - mu) : 0.f;
    float var = block_sum_192(dx * dx, red) * (1.f / DIM);
    if (t < DIM) {
        float o = dx * rsqrtf(var + 1e-6f);
        if (toXi) g_xi[n * DIM + t] = o;
        else      out[n * DIM + t] = o;
    }
}

// ---------------- launch ----------------
static inline dim3 gemm_grid(int M, int Ncols) {
    return dim3((Ncols + 127) / 128, (M + 127) / 128);
}

extern "C" void kernel_launch(void* const* d_in, const int* in_sizes, int n_in,
                              void* d_out, int out_size) {
    const int*   species  = (const int*)  d_in[0];
    const float* dist     = (const float*)d_in[1];
    const float* swtch    = (const float*)d_in[2];
    const int*   esrc     = (const int*)  d_in[3];
    const int*   edst     = (const int*)  d_in[4];
    const float* vec      = (const float*)d_in[5];
    const float* z_table  = (const float*)d_in[6];
    const float* w_sp     = (const float*)d_in[7];
    const float* pw1_0    = (const float*)d_in[8];
    const float* pb1_0    = (const float*)d_in[9];
    const float* pw2_0    = (const float*)d_in[10];
    const float* pb2_0    = (const float*)d_in[11];
    const float* wq_0     = (const float*)d_in[12];
    const float* wk_0     = (const float*)d_in[13];
    const float* wv_0     = (const float*)d_in[14];
    const float* uw_0     = (const float*)d_in[15];
    const float* ub_0     = (const float*)d_in[16];
    const float* pw1_1    = (const float*)d_in[17];
    const float* pb1_1    = (const float*)d_in[18];
    const float* pw2_1    = (const float*)d_in[19];
    const float* pb2_1    = (const float*)d_in[20];
    const float* wq_1     = (const float*)d_in[21];
    const float* wk_1     = (const float*)d_in[22];
    const float* wv_1     = (const float*)d_in[23];
    const float* uw_1     = (const float*)d_in[24];
    const float* ub_1     = (const float*)d_in[25];
    float* out = (float*)d_out;

    float *gq, *gk, *gv, *gG;
    cudaGetSymbolAddress((void**)&gq, g_q);
    cudaGetSymbolAddress((void**)&gk, g_k);
    cudaGetSymbolAddress((void**)&gv, g_v);
    cudaGetSymbolAddress((void**)&gG, g_G);
    float *gxi, *gmi;
    cudaGetSymbolAddress((void**)&gxi, g_xi);
    cudaGetSymbolAddress((void**)&gmi, g_mi);

    // node embedding + edge geometry
    node_embed_kernel<<<NN, 192>>>(species, z_table, w_sp);
    edge_geom_kernel<<<(EE + 255) / 256, 256>>>(dist, vec);

    const int EDGE_BLOCKS = 1480;
    const int ZGRID = (NN * DIM + 255) / 256;

    // ---- layer 0 ----
    sgemm_kernel<<<gemm_grid(NN, NHH * ATT), 256>>>(gxi, gxi, DIM, DIM, wq_0, gq, NN, NHH * ATT);
    sgemm_kernel<<<gemm_grid(NN, NHH * ATT), 256>>>(gxi, gxi, DIM, DIM, wk_0, gk, NN, NHH * ATT);
    sgemm_kernel<<<gemm_grid(NN, DIM), 256>>>(gxi, gxi, DIM, DIM, wv_0, gv, NN, DIM);
    zero_kernel<<<ZGRID, 256>>>(1);
    edge_attn_kernel<0><<<EDGE_BLOCKS, 256>>>(esrc, edst, swtch, pw1_0, pb1_0, pw2_0, pb2_0);
    sgemm_kernel<<<gemm_grid(NN, DIM), 256>>>(gxi, gmi, DIM, 2 * DIM, uw_0, gG, NN, DIM);
    resln_kernel<<<NN, 192>>>(ub_0, out, 1);

    // ---- layer 1 ----
    sgemm_kernel<<<gemm_grid(NN, NHH * ATT), 256>>>(gxi, gxi, DIM, DIM, wq_1, gq, NN, NHH * ATT);
    sgemm_kernel<<<gemm_grid(NN, NHH * ATT), 256>>>(gxi, gxi, DIM, DIM, wk_1, gk, NN, NHH * ATT);
    sgemm_kernel<<<gemm_grid(NN, DIM), 256>>>(gxi, gxi, DIM, DIM, wv_1, gv, NN, DIM);
    zero_kernel<<<ZGRID, 256>>>(0);
    edge_attn_kernel<1><<<EDGE_BLOCKS, 256>>>(esrc, edst, swtch, pw1_1, pb1_1, pw2_1, pb2_1);
    sgemm_kernel<<<gemm_grid(NN, DIM), 256>>>(gxi, gmi, DIM, 2 * DIM, uw_1, gG, NN, DIM);
    resln_kernel<<<NN, 192>>>(ub_1, out, 0);
}